// round 15
// baseline (speedup 1.0000x reference)
#include <cuda_runtime.h>
#include <cuda.h>
#include <cstdint>
#include <math.h>

#define BB   128
#define TIN  256
#define DIN  64
#define HH   1024
#define G4   4096
#define TOUT 128
#define DOUT 128

#define K1   (HH + DIN)   // 1088
#define NKC1 (K1 / 8)     // 136
#define NKC2 (HH / 8)     // 128
#define NCTA 128
#define NSTG 4            // A-ring stages (16KB each)

// -------------------- device scratch --------------------
__device__ float g_W1p [512 * NKC1 * 64];   // [Wh1;Wi1] permuted to B-frag order
__device__ float g_W2p [512 * NKC2 * 64];   // Wh2 permuted
__device__ float g_Wi2p[512 * NKC2 * 64];   // Wi2 permuted
__device__ float g_Wlp [ 16 * NKC2 * 64];   // Wlin permuted
__device__ __align__(256) float g_xr  [BB * TIN * DIN];
__device__ __align__(256) float g_Hbuf[2 * BB * HH];    // ping-pong hidden state
__device__ float g_C   [BB * HH];
__device__ float g_XG2 [BB * G4];
__device__ float g_HS2 [TOUT * BB * HH];
__device__ unsigned int g_bar;              // CG-style phase barrier counter

// -------------------- helpers --------------------
__device__ __forceinline__ float tf32r(float x) {
    uint32_t u;
    asm("cvt.rna.tf32.f32 %0, %1;" : "=r"(u) : "f"(x));
    return __uint_as_float(u);
}
__device__ __forceinline__ float sigf(float x) { return 1.0f / (1.0f + expf(-x)); }

__device__ __forceinline__ void mma8(float c[4], const uint32_t a[4], uint32_t b0, uint32_t b1) {
    asm volatile(
        "mma.sync.aligned.m16n8k8.row.col.f32.tf32.tf32.f32 "
        "{%0,%1,%2,%3}, {%4,%5,%6,%7}, {%8,%9}, {%0,%1,%2,%3};"
        : "+f"(c[0]), "+f"(c[1]), "+f"(c[2]), "+f"(c[3])
        : "r"(a[0]), "r"(a[1]), "r"(a[2]), "r"(a[3]), "r"(b0), "r"(b1));
}

__device__ __forceinline__ uint32_t s2u(const void* p) {
    uint32_t a;
    asm("{ .reg .u64 t; cvta.to.shared.u64 t, %1; cvt.u32.u64 %0, t; }" : "=r"(a) : "l"(p));
    return a;
}
__device__ __forceinline__ void mbar_init(uint32_t a, int cnt) {
    asm volatile("mbarrier.init.shared.b64 [%0], %1;" :: "r"(a), "r"(cnt) : "memory");
}
__device__ __forceinline__ void mbar_arrive(uint32_t a) {
    asm volatile("mbarrier.arrive.shared.b64 _, [%0];" :: "r"(a) : "memory");
}
__device__ __forceinline__ void mbar_expect(uint32_t a, uint32_t bytes) {
    asm volatile("mbarrier.arrive.expect_tx.shared.b64 _, [%0], %1;" :: "r"(a), "r"(bytes) : "memory");
}
__device__ __forceinline__ void mbar_wait(uint32_t a, int ph) {
    asm volatile(
        "{\n\t.reg .pred P;\n"
        "W%=:\n\t"
        "mbarrier.try_wait.parity.acquire.cta.shared::cta.b64 P, [%0], %1, 0x989680;\n\t"
        "@P bra D%=;\n\t"
        "bra W%=;\n"
        "D%=:\n\t}"
        :: "r"(a), "r"(ph) : "memory");
}
__device__ __forceinline__ void tma3d(uint32_t dst, const CUtensorMap* m,
                                      int x, int y, int z, uint32_t bar) {
    asm volatile(
        "cp.async.bulk.tensor.3d.shared::cta.global.tile.mbarrier::complete_tx::bytes "
        "[%0], [%1, {%2,%3,%4}], [%5];"
        :: "r"(dst), "l"(m), "r"(x), "r"(y), "r"(z), "r"(bar) : "memory");
}
__device__ __forceinline__ void fence_async() {
    asm volatile("fence.proxy.async;" ::: "memory");
}

// Cooperative-groups-style grid barrier (proven R9-R13).
__device__ __forceinline__ void grid_barrier() {
    __syncthreads();
    if (threadIdx.x == 0) {
        __threadfence();
        unsigned int nb = (blockIdx.x == 0) ? (0x80000000u - (NCTA - 1u)) : 1u;
        unsigned int old = atomicAdd(&g_bar, nb);
        volatile unsigned int* vb = &g_bar;
        while ((((old ^ *vb) & 0x80000000u) == 0u)) { }
        __threadfence();
    }
    __syncthreads();
}

// -------------------- prep kernels --------------------
__global__ void permW_kernel(const float* __restrict__ Wh, const float* __restrict__ Wx,
                             int which, int nkc, int ldsrc, int total) {
    int i = blockIdx.x * blockDim.x + threadIdx.x;
    if (i >= total) return;
    float* dst = (which == 0) ? g_W1p : (which == 1) ? g_W2p : (which == 2) ? g_Wi2p : g_Wlp;
    int reg  = i & 1;
    int lane = (i >> 1) & 31;
    int kc   = (i >> 6) % nkc;
    int nt   = i / (nkc * 64);
    int k = kc * 8 + reg * 4 + (lane & 3);
    int n = nt * 8 + (lane >> 2);
    float v = (k < HH) ? Wh[k * ldsrc + n] : Wx[(k - HH) * ldsrc + n];
    dst[i] = tf32r(v);
}

__global__ void roundx_kernel(const float* __restrict__ x, int total) {
    int i = blockIdx.x * blockDim.x + threadIdx.x;
    if (i < total) g_xr[i] = tf32r(x[i]);
}

__global__ void zero_kernel() {
    int i = blockIdx.x * blockDim.x + threadIdx.x;
    if (i < BB * HH) { g_Hbuf[i] = 0.0f; g_Hbuf[BB * HH + i] = 0.0f; g_C[i] = 0.0f; }
    if (i == 0) g_bar = 0u;
}

// -------------------- persistent LSTM layer kernel --------------------
// 128 CTAs x 160 thr, one CTA per SM (single wave -> grid barrier safe).
// WARP-SPECIALIZED: warps 0-3 = consumers (tf32 mma, M=32 rows each = 2 m16
// tiles -> crossbar-optimal wm=4/wq=1 tiling, 8KB smem traffic per k8 vs
// 12KB at wm=8), thread 128 (warp 4) = dedicated TMA producer with 4-stage
// ring of 16KB A chunks (SW128, 1024B-aligned). B fragments for chunk c are
// prefetched BEFORE the full-barrier wait (B is stage-independent). B slab
// SMEM-resident. Cell state in registers. CG grid barrier between steps;
// proxy fence orders generic h-stores before async-proxy TMA reads.
template<int LAYER>
__global__ void __launch_bounds__(160)
lstm_persist(const __grid_constant__ CUtensorMap tmH,
             const __grid_constant__ CUtensorMap tmX,
             const float* __restrict__ bias, int nsteps)
{
    constexpr int NKC = (LAYER == 1) ? NKC1 : NKC2;
    constexpr int NC  = (LAYER == 1) ? 34 : 32;     // 32-k chunks per step

    extern __shared__ float smraw[];
    const uint32_t rawB = s2u(smraw);
    const uint32_t aB   = (rawB + 1023u) & ~1023u;  // 1024B-aligned TMA ring
    float* sA = smraw + ((aB - rawB) >> 2);          // NSTG x 4096 floats
    float* sB = sA + NSTG * 4096;                    // B slab, fragment order
    const uint32_t barB = s2u(sB + 4 * NKC * 64);    // per stage: full@+0, empty@+8

    const int tid = threadIdx.x, w = tid >> 5, lane = tid & 31, cta = blockIdx.x;
    const bool producer = (tid == 128);
    const bool consumer = (tid < 128);

    // ---- load B slabs into SMEM (once per layer) ----
    {
        const float* Wp = (LAYER == 1) ? g_W1p : g_W2p;
        #pragma unroll
        for (int q = 0; q < 4; ++q) {
            const float4* src = (const float4*)(Wp + (size_t)(cta + q * 128) * (NKC * 64));
            float4* dst = (float4*)(sB + q * NKC * 64);
            for (int i = tid; i < NKC * 16; i += 160) dst[i] = src[i];
        }
    }
    if (tid == 0) {
        #pragma unroll
        for (int s = 0; s < NSTG; ++s) {
            mbar_init(barB + s * 16 + 0, 1);   // full: one expect_tx arrive
            mbar_init(barB + s * 16 + 8, 4);   // empty: 4 consumer warps
        }
        asm volatile("fence.proxy.async.shared::cta;" ::: "memory");
    }

    // ---- per-thread constants (consumers; warp w owns rows [w*32, w*32+32)) ----
    const int j0 = cta * 8 + (lane & 3) * 2;

    float bI[2], bF[2], bG[2], bO[2];
    float xg[2][4][4];          // [mt][cr][gate]
    float creg[2][4];           // [mt][cr]
    #pragma unroll
    for (int mt = 0; mt < 2; ++mt)
        #pragma unroll
        for (int cr = 0; cr < 4; ++cr) creg[mt][cr] = 0.f;

    if (consumer) {
        if (LAYER == 1) {
            #pragma unroll
            for (int u = 0; u < 2; ++u) {
                bI[u] = bias[j0 + u];          bF[u] = bias[HH + j0 + u];
                bG[u] = bias[2 * HH + j0 + u]; bO[u] = bias[3 * HH + j0 + u];
            }
        } else {
            #pragma unroll
            for (int mt = 0; mt < 2; ++mt)
                #pragma unroll
                for (int cr = 0; cr < 4; ++cr) {
                    int m = w * 32 + mt * 16 + (lane >> 2) + ((cr >> 1) << 3);
                    int j = j0 + (cr & 1);
                    xg[mt][cr][0] = __ldcg(&g_XG2[m * G4 + j]);
                    xg[mt][cr][1] = __ldcg(&g_XG2[m * G4 + HH + j]);
                    xg[mt][cr][2] = __ldcg(&g_XG2[m * G4 + 2 * HH + j]);
                    xg[mt][cr][3] = __ldcg(&g_XG2[m * G4 + 3 * HH + j]);
                    creg[mt][cr]  = __ldcg(&g_C[m * HH + j]);
                }
        }
    }
    __syncthreads();

    int ps = 0, pp = 1, cs = 0, cp = 0;   // producer / consumer stage+phase
    int rd = 0;

    for (int t = 0; t < nsteps; ++t) {
        if (producer) {
            // ---- dedicated TMA producer: stream all chunks of this step ----
            fence_async();   // order prior generic h-stores before async reads
            for (int c = 0; c < NC; ++c) {
                mbar_wait(barB + ps * 16 + 8, pp);
                mbar_expect(barB + ps * 16, 16384);
                uint32_t d = aB + ps * 16384;
                if (LAYER == 1 && c >= 32)
                    tma3d(d, &tmX, (c - 32) * 32, t, 0, barB + ps * 16);
                else
                    tma3d(d, &tmH, c * 32, 0, rd, barB + ps * 16);
                ps = (ps + 1) & (NSTG - 1); if (ps == 0) pp ^= 1;
            }
        }

        float acc[4][2][4];     // [q][mt][cr]
        #pragma unroll
        for (int q = 0; q < 4; ++q)
            #pragma unroll
            for (int mt = 0; mt < 2; ++mt)
                #pragma unroll
                for (int r = 0; r < 4; ++r) acc[q][mt][r] = 0.f;

        if (consumer) {
            for (int c = 0; c < NC; ++c) {
                // prefetch B fragments (stage-independent -> hides under wait)
                float2 bfr[4][4];
                #pragma unroll
                for (int kk = 0; kk < 4; ++kk) {
                    int kc = c * 4 + kk;
                    #pragma unroll
                    for (int q = 0; q < 4; ++q)
                        bfr[kk][q] = *(const float2*)(sB + (q * NKC + kc) * 64 + lane * 2);
                }

                mbar_wait(barB + cs * 16, cp);
                const float* hb = sA + cs * 4096;

                #pragma unroll
                for (int kk = 0; kk < 4; ++kk) {
                    uint32_t a[2][4];
                    #pragma unroll
                    for (int mt = 0; mt < 2; ++mt)
                        #pragma unroll
                        for (int r = 0; r < 4; ++r) {
                            int m    = w * 32 + mt * 16 + (lane >> 2) + (r & 1) * 8;
                            int colw = kk * 8 + (lane & 3) + ((r >> 1) << 2);
                            a[mt][r] = __float_as_uint(hb[m * 32 + (colw ^ ((m & 7) << 2))]);
                        }
                    #pragma unroll
                    for (int q = 0; q < 4; ++q)
                        #pragma unroll
                        for (int mt = 0; mt < 2; ++mt)
                            mma8(acc[q][mt], a[mt],
                                 __float_as_uint(bfr[kk][q].x), __float_as_uint(bfr[kk][q].y));
                }
                if (lane == 0) mbar_arrive(barB + cs * 16 + 8);
                cs = (cs + 1) & (NSTG - 1); if (cs == 0) cp ^= 1;
            }

            // ---- epilogue: gates, cell update (registers), publish h ----
            #pragma unroll
            for (int mt = 0; mt < 2; ++mt)
                #pragma unroll
                for (int cr = 0; cr < 4; ++cr) {
                    float gi, gf, gg, go;
                    if (LAYER == 1) {
                        gi = acc[0][mt][cr] + bI[cr & 1]; gf = acc[1][mt][cr] + bF[cr & 1];
                        gg = acc[2][mt][cr] + bG[cr & 1]; go = acc[3][mt][cr] + bO[cr & 1];
                    } else {
                        gi = acc[0][mt][cr] + xg[mt][cr][0]; gf = acc[1][mt][cr] + xg[mt][cr][1];
                        gg = acc[2][mt][cr] + xg[mt][cr][2]; go = acc[3][mt][cr] + xg[mt][cr][3];
                    }
                    float cn = sigf(gf) * creg[mt][cr] + sigf(gi) * tanhf(gg);
                    float hn = sigf(go) * tanhf(cn);
                    creg[mt][cr] = cn;
                    float hr = tf32r(hn);
                    int m = w * 32 + mt * 16 + (lane >> 2) + ((cr >> 1) << 3);
                    int j = j0 + (cr & 1);
                    __stcg(&g_Hbuf[(rd ^ 1) * (BB * HH) + m * HH + j], hr);
                    if (LAYER == 2) __stcg(&g_HS2[t * (BB * HH) + m * HH + j], hr);
                    if (LAYER == 1 && t == nsteps - 1) __stcg(&g_C[m * HH + j], cn);
                }
        }

        grid_barrier();    // proven-correct CG barrier (also syncs producer)
        rd ^= 1;
    }
}

// -------------------- one-shot GEMMs (XG2, final projection) --------------------
// MODE 2: XG2 = t_last @ Wi2 + b2   MODE 3: out = HS2 @ Wlin + blin
template<int MODE>
__global__ void __launch_bounds__(256)
gemm_kernel(const float* __restrict__ bias, float* __restrict__ out) {
    constexpr int NKC = NKC2;
    constexpr int NC  = HH / 32;

    __shared__ float sAs[2][4096];
    const int tid = threadIdx.x, w = tid >> 5, lane = tid & 31, cta = blockIdx.x;

    const float* Aptr = (MODE == 3) ? (g_HS2 + blockIdx.x * (BB * HH)) : g_Hbuf;
    const float* Wp   = (MODE == 3) ? g_Wlp : g_Wi2p;

    float acc[4][4];
    #pragma unroll
    for (int q = 0; q < 4; ++q)
        #pragma unroll
        for (int r = 0; r < 4; ++r) acc[q][r] = 0.0f;

    auto stage = [&](int c, float* dstbuf) {
        #pragma unroll
        for (int jj = 0; jj < 4; ++jj) {
            int s  = tid + jj * 256;
            int m  = s >> 3;
            int kq = s & 7;
            float4 v = *(const float4*)(Aptr + m * HH + c * 32 + kq * 4);
            int kk  = kq >> 1;
            int reg = (kq & 1) * 2 + ((m >> 3) & 1);
            int hi3 = (m & 7) ^ kq;
            *(float4*)(dstbuf + kk * 1024 + ((m >> 4) * 4 + reg) * 32 + hi3 * 4) = v;
        }
    };

    stage(0, sAs[0]);
    __syncthreads();

    for (int c = 0; c < NC; ++c) {
        const float* buf = sAs[c & 1];
        if (c + 1 < NC) stage(c + 1, sAs[(c + 1) & 1]);

        float2 bfr[4][4];
        #pragma unroll
        for (int kk = 0; kk < 4; ++kk) {
            int kc = c * 4 + kk;
            #pragma unroll
            for (int q = 0; q < 4; ++q) {
                int nt = (MODE == 3) ? (blockIdx.y * 4 + q) : (cta + q * 128);
                bfr[kk][q] = *(const float2*)(Wp + ((size_t)(nt * NKC + kc) * 32 + lane) * 2);
            }
        }

        #pragma unroll
        for (int kk = 0; kk < 4; ++kk) {
            uint32_t a[4];
            #pragma unroll
            for (int r = 0; r < 4; ++r) {
                int hi3 = (lane >> 2) ^ (kk * 2 + (r >> 1));
                a[r] = __float_as_uint(buf[kk * 1024 + (w * 4 + r) * 32 + hi3 * 4 + (lane & 3)]);
            }
            #pragma unroll
            for (int q = 0; q < 4; ++q)
                mma8(acc[q], a, __float_as_uint(bfr[kk][q].x), __float_as_uint(bfr[kk][q].y));
        }
        __syncthreads();
    }

    #pragma unroll
    for (int cr = 0; cr < 4; ++cr) {
        int m    = w * 16 + (lane >> 2) + ((cr >> 1) << 3);
        int jloc = (lane & 3) * 2 + (cr & 1);
        if (MODE == 3) {
            #pragma unroll
            for (int q = 0; q < 4; ++q) {
                int d = blockIdx.y * 32 + q * 8 + jloc;
                out[m * (TOUT * DOUT) + blockIdx.x * DOUT + d] = acc[q][cr] + bias[d];
            }
        } else {
            #pragma unroll
            for (int q = 0; q < 4; ++q) {
                int n = q * HH + cta * 8 + jloc;
                g_XG2[m * G4 + n] = acc[q][cr] + bias[n];
            }
        }
    }
}

// -------------------- launch --------------------
typedef CUresult (*EncodeFn)(CUtensorMap*, CUtensorMapDataType, cuuint32_t, void*,
                             const cuuint64_t*, const cuuint64_t*, const cuuint32_t*,
                             const cuuint32_t*, CUtensorMapInterleave, CUtensorMapSwizzle,
                             CUtensorMapL2promotion, CUtensorMapFloatOOBfill);

// smem: 1024B align slack + 64KB A ring (4x16KB) + B slab + barrier block
#define SMEM1 (1024 + 65536 + 4 * NKC1 * 64 * 4 + 128)   // 205,952 B
#define SMEM2 (1024 + 65536 + 4 * NKC2 * 64 * 4 + 128)   // 197,760 B

extern "C" void kernel_launch(void* const* d_in, const int* in_sizes, int n_in,
                              void* d_out, int out_size) {
    const float* x    = (const float*)d_in[0];
    const float* Wi1  = (const float*)d_in[1];
    const float* Wh1  = (const float*)d_in[2];
    const float* b1   = (const float*)d_in[3];
    const float* Wi2  = (const float*)d_in[4];
    const float* Wh2  = (const float*)d_in[5];
    const float* b2   = (const float*)d_in[6];
    const float* Wlin = (const float*)d_in[7];
    const float* blin = (const float*)d_in[8];
    float* out = (float*)d_out;

    // ---- prep ----
    {
        int n;
        n = 512 * NKC1 * 64;
        permW_kernel<<<(n + 255) / 256, 256>>>(Wh1, Wi1, 0, NKC1, G4, n);
        n = 512 * NKC2 * 64;
        permW_kernel<<<(n + 255) / 256, 256>>>(Wh2, nullptr, 1, NKC2, G4, n);
        permW_kernel<<<(n + 255) / 256, 256>>>(Wi2, nullptr, 2, NKC2, G4, n);
        n = 16 * NKC2 * 64;
        permW_kernel<<<(n + 255) / 256, 256>>>(Wlin, nullptr, 3, NKC2, DOUT, n);
        n = BB * TIN * DIN;
        roundx_kernel<<<(n + 255) / 256, 256>>>(x, n);
        zero_kernel<<<(BB * HH + 255) / 256, 256>>>();
    }

    // ---- tensor maps (host-side, capture-legal; R11/R13-proven) ----
    void* encP = nullptr;
    cudaDriverEntryPointQueryResult qr;
    cudaGetDriverEntryPointByVersion("cuTensorMapEncodeTiled", &encP, 12000,
                                     cudaEnableDefault, &qr);
    EncodeFn enc = (EncodeFn)encP;

    void* hAddr = nullptr; cudaGetSymbolAddress(&hAddr, g_Hbuf);
    void* xAddr = nullptr; cudaGetSymbolAddress(&xAddr, g_xr);

    CUtensorMap tmH, tmX;
    {
        // h: [1024 floats][128 rows][2 bufs]; box = 32 floats x 128 rows (16KB)
        cuuint64_t dims[3] = {1024, 128, 2};
        cuuint64_t str[2]  = {4096, 524288};
        cuuint32_t box[3]  = {32, 128, 1};
        cuuint32_t es[3]   = {1, 1, 1};
        enc(&tmH, CU_TENSOR_MAP_DATA_TYPE_FLOAT32, 3, hAddr, dims, str, box, es,
            CU_TENSOR_MAP_INTERLEAVE_NONE, CU_TENSOR_MAP_SWIZZLE_128B,
            CU_TENSOR_MAP_L2_PROMOTION_L2_128B, CU_TENSOR_MAP_FLOAT_OOB_FILL_NONE);
    }
    {
        // x: [64 floats][256 t][128 batch]; box = 32 floats x 1 t x 128 batches (16KB)
        cuuint64_t dims[3] = {64, 256, 128};
        cuuint64_t str[2]  = {256, 65536};
        cuuint32_t box[3]  = {32, 1, 128};
        cuuint32_t es[3]   = {1, 1, 1};
        enc(&tmX, CU_TENSOR_MAP_DATA_TYPE_FLOAT32, 3, xAddr, dims, str, box, es,
            CU_TENSOR_MAP_INTERLEAVE_NONE, CU_TENSOR_MAP_SWIZZLE_128B,
            CU_TENSOR_MAP_L2_PROMOTION_L2_128B, CU_TENSOR_MAP_FLOAT_OOB_FILL_NONE);
    }

    cudaFuncSetAttribute(lstm_persist<1>, cudaFuncAttributeMaxDynamicSharedMemorySize, SMEM1);
    cudaFuncSetAttribute(lstm_persist<2>, cudaFuncAttributeMaxDynamicSharedMemorySize, SMEM2);

    // ---- layer 1: 256 steps, persistent, warp-specialized ----
    lstm_persist<1><<<NCTA, 160, SMEM1>>>(tmH, tmX, b1, TIN);
    // ---- xg2 = t_last @ Wi2 + b2 (t_last = g_Hbuf buffer 0 after 256 steps) ----
    gemm_kernel<2><<<128, 256>>>(b2, nullptr);
    // ---- layer 2: 128 steps, persistent (h,c carry over) ----
    lstm_persist<2><<<NCTA, 160, SMEM2>>>(tmH, tmX, nullptr, TOUT);
    // ---- final projection ----
    gemm_kernel<3><<<dim3(TOUT, 4), 256>>>(blin, out);
}

// round 16
// speedup vs baseline: 1.6227x; 1.6227x over previous
#include <cuda_runtime.h>
#include <cuda.h>
#include <cuda_fp16.h>
#include <cstdint>
#include <math.h>

#define BB   128
#define TIN  256
#define DIN  64
#define HH   1024
#define G4   4096
#define TOUT 128
#define DOUT 128

#define K1   (HH + DIN)   // 1088
#define NKT1 (K1 / 16)    // 68 k16-tiles, layer 1
#define NKT2 (HH / 16)    // 64
#define NKC2 (HH / 8)     // legacy tf32 layout (modes 2/3)
#define NCTA 128
#define NSTG 4            // A-ring stages (16KB each)

// -------------------- device scratch --------------------
__device__ uint32_t g_W1h [512 * NKT1 * 64];  // [Wh1;Wi1] fp16-pair frag order
__device__ uint32_t g_W2h [512 * NKT2 * 64];  // Wh2
__device__ float    g_Wi2p[512 * NKC2 * 64];  // legacy tf32 (mode 2)
__device__ float    g_Wlp [ 16 * NKC2 * 64];  // legacy tf32 (mode 3)
__device__ __align__(256) __half g_xr16 [BB * TIN * DIN];
__device__ __align__(256) __half g_Hbuf16[2 * BB * HH];  // fp16 ping-pong h
__device__ float g_Hf32[BB * HH];             // t_last as float (mode 2 input)
__device__ float g_C   [BB * HH];
__device__ float g_XG2 [BB * G4];
__device__ float g_HS2 [TOUT * BB * HH];
__device__ unsigned int g_bar;

// -------------------- helpers --------------------
__device__ __forceinline__ float tf32r(float x) {
    uint32_t u;
    asm("cvt.rna.tf32.f32 %0, %1;" : "=r"(u) : "f"(x));
    return __uint_as_float(u);
}
__device__ __forceinline__ float sigf(float x) { return 1.0f / (1.0f + expf(-x)); }

__device__ __forceinline__ void mma8(float c[4], const uint32_t a[4], uint32_t b0, uint32_t b1) {
    asm volatile(
        "mma.sync.aligned.m16n8k8.row.col.f32.tf32.tf32.f32 "
        "{%0,%1,%2,%3}, {%4,%5,%6,%7}, {%8,%9}, {%0,%1,%2,%3};"
        : "+f"(c[0]), "+f"(c[1]), "+f"(c[2]), "+f"(c[3])
        : "r"(a[0]), "r"(a[1]), "r"(a[2]), "r"(a[3]), "r"(b0), "r"(b1));
}
__device__ __forceinline__ void mma16(float c[4], const uint32_t a[4], uint32_t b0, uint32_t b1) {
    asm volatile(
        "mma.sync.aligned.m16n8k16.row.col.f32.f16.f16.f32 "
        "{%0,%1,%2,%3}, {%4,%5,%6,%7}, {%8,%9}, {%0,%1,%2,%3};"
        : "+f"(c[0]), "+f"(c[1]), "+f"(c[2]), "+f"(c[3])
        : "r"(a[0]), "r"(a[1]), "r"(a[2]), "r"(a[3]), "r"(b0), "r"(b1));
}

__device__ __forceinline__ uint32_t s2u(const void* p) {
    uint32_t a;
    asm("{ .reg .u64 t; cvta.to.shared.u64 t, %1; cvt.u32.u64 %0, t; }" : "=r"(a) : "l"(p));
    return a;
}
__device__ __forceinline__ void mbar_init(uint32_t a, int cnt) {
    asm volatile("mbarrier.init.shared.b64 [%0], %1;" :: "r"(a), "r"(cnt) : "memory");
}
__device__ __forceinline__ void mbar_arrive(uint32_t a) {
    asm volatile("mbarrier.arrive.shared.b64 _, [%0];" :: "r"(a) : "memory");
}
__device__ __forceinline__ void mbar_expect(uint32_t a, uint32_t bytes) {
    asm volatile("mbarrier.arrive.expect_tx.shared.b64 _, [%0], %1;" :: "r"(a), "r"(bytes) : "memory");
}
__device__ __forceinline__ void mbar_wait(uint32_t a, int ph) {
    asm volatile(
        "{\n\t.reg .pred P;\n"
        "W%=:\n\t"
        "mbarrier.try_wait.parity.acquire.cta.shared::cta.b64 P, [%0], %1, 0x989680;\n\t"
        "@P bra D%=;\n\t"
        "bra W%=;\n"
        "D%=:\n\t}"
        :: "r"(a), "r"(ph) : "memory");
}
__device__ __forceinline__ void tma3d(uint32_t dst, const CUtensorMap* m,
                                      int x, int y, int z, uint32_t bar) {
    asm volatile(
        "cp.async.bulk.tensor.3d.shared::cta.global.tile.mbarrier::complete_tx::bytes "
        "[%0], [%1, {%2,%3,%4}], [%5];"
        :: "r"(dst), "l"(m), "r"(x), "r"(y), "r"(z), "r"(bar) : "memory");
}
__device__ __forceinline__ void fence_async() {
    asm volatile("fence.proxy.async;" ::: "memory");
}

// Cooperative-groups-style grid barrier (proven R9-R15).
__device__ __forceinline__ void grid_barrier() {
    __syncthreads();
    if (threadIdx.x == 0) {
        __threadfence();
        unsigned int nb = (blockIdx.x == 0) ? (0x80000000u - (NCTA - 1u)) : 1u;
        unsigned int old = atomicAdd(&g_bar, nb);
        volatile unsigned int* vb = &g_bar;
        while ((((old ^ *vb) & 0x80000000u) == 0u)) { }
        __threadfence();
    }
    __syncthreads();
}

// -------------------- prep kernels --------------------
// fp16 m16n8k16 B-fragment order:
//   dst[((nt*nkt + kt)*32 + lane)*2 + reg] packs halves for
//   k = kt*16 + reg*8 + (lane&3)*2 (+1), n = nt*8 + (lane>>2); k-low in low half.
__global__ void permWh_kernel(const float* __restrict__ Wh, const float* __restrict__ Wx,
                              int which, int nkt, int total) {
    int i = blockIdx.x * blockDim.x + threadIdx.x;
    if (i >= total) return;
    uint32_t* dst = (which == 0) ? g_W1h : g_W2h;
    int reg  = i & 1;
    int lane = (i >> 1) & 31;
    int kt   = (i >> 6) % nkt;
    int nt   = i / (nkt * 64);
    int k = kt * 16 + reg * 8 + (lane & 3) * 2;
    int n = nt * 8 + (lane >> 2);
    float v0 = (k     < HH) ? Wh[k * G4 + n]           : Wx[(k - HH) * G4 + n];
    float v1 = (k + 1 < HH) ? Wh[(k + 1) * G4 + n]     : Wx[(k + 1 - HH) * G4 + n];
    uint32_t u = ((uint32_t)__half_as_ushort(__float2half_rn(v1)) << 16)
               |  (uint32_t)__half_as_ushort(__float2half_rn(v0));
    dst[i] = u;
}

// legacy tf32 fragment permute (modes 2/3)
__global__ void permW_kernel(const float* __restrict__ W, int which, int nkc, int ldsrc, int total) {
    int i = blockIdx.x * blockDim.x + threadIdx.x;
    if (i >= total) return;
    float* dst = (which == 2) ? g_Wi2p : g_Wlp;
    int reg  = i & 1;
    int lane = (i >> 1) & 31;
    int kc   = (i >> 6) % nkc;
    int nt   = i / (nkc * 64);
    int k = kc * 8 + reg * 4 + (lane & 3);
    int n = nt * 8 + (lane >> 2);
    dst[i] = tf32r(W[k * ldsrc + n]);
}

__global__ void roundx_kernel(const float* __restrict__ x, int total) {
    int i = blockIdx.x * blockDim.x + threadIdx.x;
    if (i < total) g_xr16[i] = __float2half_rn(x[i]);
}

__global__ void zero_kernel() {
    int i = blockIdx.x * blockDim.x + threadIdx.x;
    if (i < BB * HH) {   // BB*HH == 131072 == uint32 count of the fp16 ping-pong
        ((uint32_t*)g_Hbuf16)[i] = 0u;
        g_C[i] = 0.0f;
    }
    if (i == 0) g_bar = 0u;
}

// -------------------- persistent LSTM layer kernel (fp16 datapath) --------------------
// 128 CTAs x 288 thr, one CTA per SM. Warps 0-7 consume (M=16 rows each,
// fp16 m16n8k16 mma, fp32 accum), thread 256 = TMA producer, 4-stage ring of
// 16KB chunks (64 fp16 k-cols x 128 rows, SW128, 1024B-aligned; pair-unit
// swizzle formula identical to the proven float case). B slab (fp16 frag
// pairs) SMEM-resident. Cell state fp32 in registers. CG grid barrier;
// proxy fence orders generic h-stores before async-proxy TMA reads.
template<int LAYER>
__global__ void __launch_bounds__(288)
lstm_persist(const __grid_constant__ CUtensorMap tmH,
             const __grid_constant__ CUtensorMap tmX,
             const float* __restrict__ bias, int nsteps)
{
    constexpr int NKT = (LAYER == 1) ? NKT1 : NKT2;   // k16-tiles
    constexpr int NC  = (LAYER == 1) ? 17 : 16;       // 64-k chunks per step

    extern __shared__ float smraw[];
    const uint32_t rawB = s2u(smraw);
    const uint32_t aB   = (rawB + 1023u) & ~1023u;   // 1024B-aligned TMA ring
    uint32_t* sA  = (uint32_t*)(smraw + ((aB - rawB) >> 2));  // NSTG x 4096 u32
    uint32_t* sBh = sA + NSTG * 4096;                // B slab, frag pairs
    const uint32_t barB = s2u(sBh + 4 * NKT * 64);   // per stage: full@+0, empty@+8

    const int tid = threadIdx.x, w = tid >> 5, lane = tid & 31, cta = blockIdx.x;
    const bool producer = (tid == 256);
    const bool consumer = (tid < 256);

    // ---- load B slab into SMEM (once per layer) ----
    {
        const uint32_t* Wp = (LAYER == 1) ? g_W1h : g_W2h;
        #pragma unroll
        for (int q = 0; q < 4; ++q) {
            const uint4* src = (const uint4*)(Wp + (size_t)(cta + q * 128) * (NKT * 64));
            uint4* dst = (uint4*)(sBh + q * NKT * 64);
            for (int i = tid; i < NKT * 16; i += 288) dst[i] = src[i];
        }
    }
    if (tid == 0) {
        #pragma unroll
        for (int s = 0; s < NSTG; ++s) {
            mbar_init(barB + s * 16 + 0, 1);   // full: one expect_tx arrive
            mbar_init(barB + s * 16 + 8, 8);   // empty: 8 consumer warps
        }
        asm volatile("fence.proxy.async.shared::cta;" ::: "memory");
    }

    // ---- per-thread constants ----
    const int j0 = cta * 8 + (lane & 3) * 2;
    int mrow[4];
    #pragma unroll
    for (int cr = 0; cr < 4; ++cr) mrow[cr] = (w & 7) * 16 + (lane >> 2) + ((cr >> 1) << 3);

    float bI[2], bF[2], bG[2], bO[2];
    float xg[4][4];
    float creg[4] = {0.f, 0.f, 0.f, 0.f};
    if (consumer) {
        if (LAYER == 1) {
            #pragma unroll
            for (int u = 0; u < 2; ++u) {
                bI[u] = bias[j0 + u];          bF[u] = bias[HH + j0 + u];
                bG[u] = bias[2 * HH + j0 + u]; bO[u] = bias[3 * HH + j0 + u];
            }
        } else {
            #pragma unroll
            for (int cr = 0; cr < 4; ++cr) {
                int m = mrow[cr], j = j0 + (cr & 1);
                xg[cr][0] = __ldcg(&g_XG2[m * G4 + j]);
                xg[cr][1] = __ldcg(&g_XG2[m * G4 + HH + j]);
                xg[cr][2] = __ldcg(&g_XG2[m * G4 + 2 * HH + j]);
                xg[cr][3] = __ldcg(&g_XG2[m * G4 + 3 * HH + j]);
                creg[cr]  = __ldcg(&g_C[m * HH + j]);
            }
        }
    }
    __syncthreads();

    int ps = 0, pp = 1, cs = 0, cp = 0;   // producer / consumer stage+phase
    int rd = 0;

    for (int t = 0; t < nsteps; ++t) {
        if (producer) {
            fence_async();   // order prior generic h-stores before async reads
            for (int c = 0; c < NC; ++c) {
                mbar_wait(barB + ps * 16 + 8, pp);
                mbar_expect(barB + ps * 16, 16384);
                uint32_t d = aB + ps * 16384;
                if (LAYER == 1 && c == 16)
                    tma3d(d, &tmX, 0, t, 0, barB + ps * 16);
                else
                    tma3d(d, &tmH, c * 64, 0, rd, barB + ps * 16);
                ps = (ps + 1) & (NSTG - 1); if (ps == 0) pp ^= 1;
            }
        }

        float acc[4][4];
        #pragma unroll
        for (int q = 0; q < 4; ++q)
            #pragma unroll
            for (int r = 0; r < 4; ++r) acc[q][r] = 0.f;

        if (consumer) {
            const int g  = lane >> 2;
            const int lp = lane & 3;
            const int m0 = (w & 7) * 16 + g;
            const int m1 = m0 + 8;
            const int sw0 = (m0 & 7) << 2;
            const int sw1 = (m1 & 7) << 2;

            for (int c = 0; c < NC; ++c) {
                // prefetch B fragment pairs (stage-independent)
                uint2 bfr[4][4];
                #pragma unroll
                for (int kk = 0; kk < 4; ++kk) {
                    int kt = c * 4 + kk;
                    #pragma unroll
                    for (int q = 0; q < 4; ++q)
                        bfr[kk][q] = *(const uint2*)(sBh + ((q * NKT + kt) * 32 + lane) * 2);
                }

                mbar_wait(barB + cs * 16, cp);
                const uint32_t* hb = sA + cs * 4096;   // 128 rows x 32 pairs

                #pragma unroll
                for (int kk = 0; kk < 4; ++kk) {
                    int p0 = kk * 8 + lp;     // fp16-pair index, k-low
                    int p2 = p0 + 4;          // k+8
                    uint32_t a[4];
                    a[0] = hb[m0 * 32 + (p0 ^ sw0)];
                    a[1] = hb[m1 * 32 + (p0 ^ sw1)];
                    a[2] = hb[m0 * 32 + (p2 ^ sw0)];
                    a[3] = hb[m1 * 32 + (p2 ^ sw1)];
                    #pragma unroll
                    for (int q = 0; q < 4; ++q)
                        mma16(acc[q], a, bfr[kk][q].x, bfr[kk][q].y);
                }
                if (lane == 0) mbar_arrive(barB + cs * 16 + 8);
                cs = (cs + 1) & (NSTG - 1); if (cs == 0) cp ^= 1;
            }

            // ---- epilogue: gates, cell update (fp32 regs), publish h (fp16) ----
            #pragma unroll
            for (int cr = 0; cr < 4; ++cr) {
                float gi, gf, gg, go;
                if (LAYER == 1) {
                    gi = acc[0][cr] + bI[cr & 1]; gf = acc[1][cr] + bF[cr & 1];
                    gg = acc[2][cr] + bG[cr & 1]; go = acc[3][cr] + bO[cr & 1];
                } else {
                    gi = acc[0][cr] + xg[cr][0]; gf = acc[1][cr] + xg[cr][1];
                    gg = acc[2][cr] + xg[cr][2]; go = acc[3][cr] + xg[cr][3];
                }
                float cn = sigf(gf) * creg[cr] + sigf(gi) * tanhf(gg);
                float hn = sigf(go) * tanhf(cn);
                creg[cr] = cn;
                int m = mrow[cr], j = j0 + (cr & 1);
                __half hh = __float2half_rn(hn);
                g_Hbuf16[(rd ^ 1) * (BB * HH) + m * HH + j] = hh;
                if (LAYER == 2) __stcg(&g_HS2[t * (BB * HH) + m * HH + j], hn);
                if (LAYER == 1 && t == nsteps - 1) {
                    __stcg(&g_C[m * HH + j], cn);
                    __stcg(&g_Hf32[m * HH + j], hn);
                }
            }
        }

        grid_barrier();
        rd ^= 1;
    }
}

// -------------------- one-shot GEMMs (tf32 legacy; verbatim-proven) --------------------
// MODE 2: XG2 = t_last @ Wi2 + b2 (A = g_Hf32)   MODE 3: out = HS2 @ Wlin + blin
template<int MODE>
__global__ void __launch_bounds__(256)
gemm_kernel(const float* __restrict__ bias, float* __restrict__ out) {
    constexpr int NKC = NKC2;
    constexpr int NC  = HH / 32;

    __shared__ float sAs[2][4096];
    const int tid = threadIdx.x, w = tid >> 5, lane = tid & 31, cta = blockIdx.x;

    const float* Aptr = (MODE == 3) ? (g_HS2 + blockIdx.x * (BB * HH)) : g_Hf32;
    const float* Wp   = (MODE == 3) ? g_Wlp : g_Wi2p;

    float acc[4][4];
    #pragma unroll
    for (int q = 0; q < 4; ++q)
        #pragma unroll
        for (int r = 0; r < 4; ++r) acc[q][r] = 0.0f;

    auto stage = [&](int c, float* dstbuf) {
        #pragma unroll
        for (int jj = 0; jj < 4; ++jj) {
            int s  = tid + jj * 256;
            int m  = s >> 3;
            int kq = s & 7;
            float4 v = *(const float4*)(Aptr + m * HH + c * 32 + kq * 4);
            int kk  = kq >> 1;
            int reg = (kq & 1) * 2 + ((m >> 3) & 1);
            int hi3 = (m & 7) ^ kq;
            *(float4*)(dstbuf + kk * 1024 + ((m >> 4) * 4 + reg) * 32 + hi3 * 4) = v;
        }
    };

    stage(0, sAs[0]);
    __syncthreads();

    for (int c = 0; c < NC; ++c) {
        const float* buf = sAs[c & 1];
        if (c + 1 < NC) stage(c + 1, sAs[(c + 1) & 1]);

        float2 bfr[4][4];
        #pragma unroll
        for (int kk = 0; kk < 4; ++kk) {
            int kc = c * 4 + kk;
            #pragma unroll
            for (int q = 0; q < 4; ++q) {
                int nt = (MODE == 3) ? (blockIdx.y * 4 + q) : (cta + q * 128);
                bfr[kk][q] = *(const float2*)(Wp + ((size_t)(nt * NKC + kc) * 32 + lane) * 2);
            }
        }

        #pragma unroll
        for (int kk = 0; kk < 4; ++kk) {
            uint32_t a[4];
            #pragma unroll
            for (int r = 0; r < 4; ++r) {
                int hi3 = (lane >> 2) ^ (kk * 2 + (r >> 1));
                a[r] = __float_as_uint(buf[kk * 1024 + (w * 4 + r) * 32 + hi3 * 4 + (lane & 3)]);
            }
            #pragma unroll
            for (int q = 0; q < 4; ++q)
                mma8(acc[q], a, __float_as_uint(bfr[kk][q].x), __float_as_uint(bfr[kk][q].y));
        }
        __syncthreads();
    }

    #pragma unroll
    for (int cr = 0; cr < 4; ++cr) {
        int m    = w * 16 + (lane >> 2) + ((cr >> 1) << 3);
        int jloc = (lane & 3) * 2 + (cr & 1);
        if (MODE == 3) {
            #pragma unroll
            for (int q = 0; q < 4; ++q) {
                int d = blockIdx.y * 32 + q * 8 + jloc;
                out[m * (TOUT * DOUT) + blockIdx.x * DOUT + d] = acc[q][cr] + bias[d];
            }
        } else {
            #pragma unroll
            for (int q = 0; q < 4; ++q) {
                int n = q * HH + cta * 8 + jloc;
                g_XG2[m * G4 + n] = acc[q][cr] + bias[n];
            }
        }
    }
}

// -------------------- launch --------------------
typedef CUresult (*EncodeFn)(CUtensorMap*, CUtensorMapDataType, cuuint32_t, void*,
                             const cuuint64_t*, const cuuint64_t*, const cuuint32_t*,
                             const cuuint32_t*, CUtensorMapInterleave, CUtensorMapSwizzle,
                             CUtensorMapL2promotion, CUtensorMapFloatOOBfill);

// smem: align slack + 64KB A ring + fp16 B slab + barrier block
#define SMEM1 (1024 + 65536 + 4 * NKT1 * 64 * 4 + 128)   // 136,320 B
#define SMEM2 (1024 + 65536 + 4 * NKT2 * 64 * 4 + 128)   // 132,224 B

extern "C" void kernel_launch(void* const* d_in, const int* in_sizes, int n_in,
                              void* d_out, int out_size) {
    const float* x    = (const float*)d_in[0];
    const float* Wi1  = (const float*)d_in[1];
    const float* Wh1  = (const float*)d_in[2];
    const float* b1   = (const float*)d_in[3];
    const float* Wi2  = (const float*)d_in[4];
    const float* Wh2  = (const float*)d_in[5];
    const float* b2   = (const float*)d_in[6];
    const float* Wlin = (const float*)d_in[7];
    const float* blin = (const float*)d_in[8];
    float* out = (float*)d_out;

    // ---- prep ----
    {
        int n;
        n = 512 * NKT1 * 64;
        permWh_kernel<<<(n + 255) / 256, 256>>>(Wh1, Wi1, 0, NKT1, n);
        n = 512 * NKT2 * 64;
        permWh_kernel<<<(n + 255) / 256, 256>>>(Wh2, nullptr, 1, NKT2, n);
        n = 512 * NKC2 * 64;
        permW_kernel<<<(n + 255) / 256, 256>>>(Wi2, 2, NKC2, G4, n);
        n = 16 * NKC2 * 64;
        permW_kernel<<<(n + 255) / 256, 256>>>(Wlin, 3, NKC2, DOUT, n);
        n = BB * TIN * DIN;
        roundx_kernel<<<(n + 255) / 256, 256>>>(x, n);
        zero_kernel<<<(BB * HH + 255) / 256, 256>>>();
    }

    // ---- tensor maps (fp16; SW128 box = 64 halves = 128 B) ----
    void* encP = nullptr;
    cudaDriverEntryPointQueryResult qr;
    cudaGetDriverEntryPointByVersion("cuTensorMapEncodeTiled", &encP, 12000,
                                     cudaEnableDefault, &qr);
    EncodeFn enc = (EncodeFn)encP;

    void* hAddr = nullptr; cudaGetSymbolAddress(&hAddr, g_Hbuf16);
    void* xAddr = nullptr; cudaGetSymbolAddress(&xAddr, g_xr16);

    CUtensorMap tmH, tmX;
    {
        // h: [1024 halves][128 rows][2 bufs]; box = 64 halves x 128 rows (16KB)
        cuuint64_t dims[3] = {1024, 128, 2};
        cuuint64_t str[2]  = {2048, 262144};
        cuuint32_t box[3]  = {64, 128, 1};
        cuuint32_t es[3]   = {1, 1, 1};
        enc(&tmH, CU_TENSOR_MAP_DATA_TYPE_UINT16, 3, hAddr, dims, str, box, es,
            CU_TENSOR_MAP_INTERLEAVE_NONE, CU_TENSOR_MAP_SWIZZLE_128B,
            CU_TENSOR_MAP_L2_PROMOTION_L2_128B, CU_TENSOR_MAP_FLOAT_OOB_FILL_NONE);
    }
    {
        // x: [64 halves][256 t][128 batch]; box = 64 x 1 x 128 (16KB)
        cuuint64_t dims[3] = {64, 256, 128};
        cuuint64_t str[2]  = {128, 32768};
        cuuint32_t box[3]  = {64, 1, 128};
        cuuint32_t es[3]   = {1, 1, 1};
        enc(&tmX, CU_TENSOR_MAP_DATA_TYPE_UINT16, 3, xAddr, dims, str, box, es,
            CU_TENSOR_MAP_INTERLEAVE_NONE, CU_TENSOR_MAP_SWIZZLE_128B,
            CU_TENSOR_MAP_L2_PROMOTION_L2_128B, CU_TENSOR_MAP_FLOAT_OOB_FILL_NONE);
    }

    cudaFuncSetAttribute(lstm_persist<1>, cudaFuncAttributeMaxDynamicSharedMemorySize, SMEM1);
    cudaFuncSetAttribute(lstm_persist<2>, cudaFuncAttributeMaxDynamicSharedMemorySize, SMEM2);

    // ---- layer 1: 256 steps, persistent, warp-specialized, fp16 datapath ----
    lstm_persist<1><<<NCTA, 288, SMEM1>>>(tmH, tmX, b1, TIN);
    // ---- xg2 = t_last @ Wi2 + b2 (t_last saved as float in g_Hf32) ----
    gemm_kernel<2><<<128, 256>>>(b2, nullptr);
    // ---- layer 2: 128 steps, persistent (h,c carry over; h buf 0 = fp16 hT) ----
    lstm_persist<2><<<NCTA, 288, SMEM2>>>(tmH, tmX, nullptr, TOUT);
    // ---- final projection ----
    gemm_kernel<3><<<dim3(TOUT, 4), 256>>>(blin, out);
}